// round 15
// baseline (speedup 1.0000x reference)
#include <cuda_runtime.h>
#include <cuda_bf16.h>

// ONE kernel, ZERO inter-block sync. n=1024, K=8 -> 8192 entries.
//   total = sum_{a in pos, b in neg} log(1 + exp(v_b - v_a)) / (P*N)
//
// Tile decomposition: 16 ranges x 512 entries = 8192 EXACTLY (no bounds
// checks). Block b=(i,j) compacts positives of range i and negatives of
// range j into SMEM in ONE pass (1 pos + 1 neg element per thread), then
// computes its pos-tile x neg-tile pairs. 256 blocks cover every cross pair
// exactly once -> no grid barrier, no multi-kernel graph. 2 CTAs/SM, 1 wave.
//
// Pair math (validated rel_err ~1e-7):
//   exp(q-p) = exp(q)*exp(-p);  sum log(1+t) = (sum log2 prod(t/64)+corr)*ln2
//   fma.rn.f32x2 / mul.rn.f32x2 packed: 1 instruction covers 2 pairs.
// Positives lane-broadcast (pk2(F,F) once/unit); negatives consumed directly
// as u64 lane-pairs (ulonglong2 smem loads). Zero-padded slots give
// t' = 1/64 whose log2 exactly cancels the +6/pair correction.

#define RNG    16
#define RSZ    512            // 16*512 = 8192 exactly
#define GRID   (RNG * RNG)    // 256 <= 148*2 (one wave)
#define TPB    512
#define WARPS  (TPB / 32)
#define LCAP   544            // >= RSZ + 32 pad, multiple of 32
#define NSLOT  16

__device__ unsigned int g_P;        // global positive count   (reset per call)
__device__ unsigned int g_N;        // global negative count   (reset per call)
__device__ unsigned int g_done;     // finished blocks         (reset per call)
__device__ double g_accSlot[NSLOT];

typedef unsigned long long u64;

__device__ __forceinline__ u64 pk2(float lo, float hi) {
    u64 r; asm("mov.b64 %0, {%1, %2};" : "=l"(r) : "f"(lo), "f"(hi)); return r;
}
__device__ __forceinline__ void upk2(u64 v, float& lo, float& hi) {
    asm("mov.b64 {%0, %1}, %2;" : "=f"(lo), "=f"(hi) : "l"(v));
}
__device__ __forceinline__ u64 fma2(u64 a, u64 b, u64 c) {
    u64 d; asm("fma.rn.f32x2 %0, %1, %2, %3;" : "=l"(d) : "l"(a), "l"(b), "l"(c));
    return d;
}
__device__ __forceinline__ u64 mul2(u64 a, u64 b) {
    u64 d; asm("mul.rn.f32x2 %0, %1, %2;" : "=l"(d) : "l"(a), "l"(b));
    return d;
}

__global__ void __launch_bounds__(TPB, 2)
rul_tile_kernel(const float* __restrict__ pred,
                const int* __restrict__ label,
                int total,
                float* __restrict__ out) {
    __shared__ __align__(16) float sPos[LCAP];   // exp(-v) list, zero padded
    __shared__ __align__(16) float sNeg[LCAP];   // exp(+v) list, zero padded
    __shared__ unsigned int sCntP, sCntN;
    __shared__ float sRed[WARPS];

    const unsigned lane = threadIdx.x & 31u;
    const unsigned warp = threadIdx.x >> 5;
    const unsigned ltmask = (1u << lane) - 1u;
    const int pi = blockIdx.x / RNG;     // positive range index
    const int nj = blockIdx.x % RNG;     // negative range index

    // ---- zero lists + counters ---------------------------------------------
    for (int k = (int)threadIdx.x; k < LCAP; k += TPB) {
        sPos[k] = 0.0f; sNeg[k] = 0.0f;
    }
    if (threadIdx.x == 0) { sCntP = 0u; sCntN = 0u; }
    __syncthreads();

    // ---- single-pass compaction: 1 pos + 1 neg element per thread ----------
    {
        int idx = (int)threadIdx.x;
        float vp = pred[pi * RSZ + idx];
        int   yp = label[pi * RSZ + idx];
        float vn = pred[nj * RSZ + idx];
        int   yn = label[nj * RSZ + idx];
        bool isPos = (yp == 1);
        bool isNeg = (yn == 0);

        unsigned mp = __ballot_sync(0xFFFFFFFFu, isPos);
        unsigned mn = __ballot_sync(0xFFFFFFFFu, isNeg);
        unsigned bp = 0, bn = 0;
        if (lane == 0) {
            if (mp) bp = atomicAdd(&sCntP, (unsigned)__popc(mp));
            if (mn) bn = atomicAdd(&sCntN, (unsigned)__popc(mn));
        }
        bp = __shfl_sync(0xFFFFFFFFu, bp, 0);
        bn = __shfl_sync(0xFFFFFFFFu, bn, 0);
        if (isPos) sPos[bp + __popc(mp & ltmask)] = __expf(-vp);
        if (isNeg) sNeg[bn + __popc(mn & ltmask)] = __expf(vn);
    }
    __syncthreads();

    const int cntP = (int)sCntP;
    const int cntN = (int)sCntN;

    // Contribute local counts to global P,N (each range counted once).
    if (threadIdx.x == 0) {
        if (nj == 0 && cntP) atomicAdd(&g_P, (unsigned)cntP);
        if (pi == 0 && cntN) atomicAdd(&g_N, (unsigned)cntN);
    }

    // ---- pair phase: 4 positives x 32 negatives per unit ---------------------
    int G4 = (cntP + 3) >> 2;                 // pos groups of 4
    if (G4 < 1) G4 = 1;
    int nCh = (cntN + 31) >> 5;               // neg chunks of 32 (8 ull2)
    const int units = G4 * nCh;               // ~512 typical (1/thread)

    const float4* __restrict__ posf4 =
        reinterpret_cast<const float4*>(sPos);
    const ulonglong2* __restrict__ negu =
        reinterpret_cast<const ulonglong2*>(sNeg);  // 1 ull2 = 4 negs
    const u64 S2 = pk2(0.015625f, 0.015625f); // 1/64

    float lgSum = 0.0f;
    int   nUnits = 0;
    for (int u = (int)threadIdx.x; u < units; u += TPB) {
        int chunk = u / G4;                   // consecutive threads share chunk
        int pg    = u - chunk * G4;

        float4 Fa = posf4[pg];                // 4 positives, coalesced
        u64 F0 = mul2(pk2(Fa.x, Fa.x), S2);   // lane-broadcast F/64
        u64 F1 = mul2(pk2(Fa.y, Fa.y), S2);
        u64 F2 = mul2(pk2(Fa.z, Fa.z), S2);
        u64 F3 = mul2(pk2(Fa.w, Fa.w), S2);

        const ulonglong2* qp = negu + chunk * 8;
        u64 m0, m1, m2, m3;
        {
            ulonglong2 qq = qp[0];
            m0 = mul2(fma2(qq.x, F0, S2), fma2(qq.y, F0, S2));
            m1 = mul2(fma2(qq.x, F1, S2), fma2(qq.y, F1, S2));
            m2 = mul2(fma2(qq.x, F2, S2), fma2(qq.y, F2, S2));
            m3 = mul2(fma2(qq.x, F3, S2), fma2(qq.y, F3, S2));
        }
#pragma unroll
        for (int k = 1; k < 8; ++k) {
            ulonglong2 qq = qp[k];
            m0 = mul2(m0, mul2(fma2(qq.x, F0, S2), fma2(qq.y, F0, S2)));
            m1 = mul2(m1, mul2(fma2(qq.x, F1, S2), fma2(qq.y, F1, S2)));
            m2 = mul2(m2, mul2(fma2(qq.x, F2, S2), fma2(qq.y, F2, S2)));
            m3 = mul2(m3, mul2(fma2(qq.x, F3, S2), fma2(qq.y, F3, S2)));
        }
        float a, b;
        upk2(m0, a, b); lgSum += __log2f(a) + __log2f(b);
        upk2(m1, a, b); lgSum += __log2f(a) + __log2f(b);
        upk2(m2, a, b); lgSum += __log2f(a) + __log2f(b);
        upk2(m3, a, b); lgSum += __log2f(a) + __log2f(b);
        ++nUnits;
    }
    // Each unit: 8 scalar chains of 16 t' values; +16*log2(64)=96 per chain
    // -> +768 per unit. Zero pads contribute log2(1/64) = -6 each, exactly
    // cancelled by the same correction.
    float threadSum = (lgSum + 768.0f * (float)nUnits) * 0.6931471805599453f;

    // ---- block reduction ------------------------------------------------------
#pragma unroll
    for (int off = 16; off > 0; off >>= 1)
        threadSum += __shfl_down_sync(0xFFFFFFFFu, threadSum, off);
    if (lane == 0) sRed[warp] = threadSum;
    __syncthreads();
    if (warp == 0) {
        float s = (lane < WARPS) ? sRed[lane] : 0.0f;
#pragma unroll
        for (int off = 16; off > 0; off >>= 1)
            s += __shfl_down_sync(0xFFFFFFFFu, s, off);

        // ---- slotted accumulate + last-block finalize --------------------------
        if (lane == 0) {
            atomicAdd(&g_accSlot[blockIdx.x & (NSLOT - 1)], (double)s);
            __threadfence();
            unsigned int d = atomicAdd(&g_done, 1u);
            if (d == GRID - 1) {
                __threadfence();
                double acc = 0.0;
#pragma unroll
                for (int k = 0; k < NSLOT; ++k) {
                    acc += *(volatile double*)&g_accSlot[k];
                    g_accSlot[k] = 0.0;
                }
                double P = (double)*(volatile unsigned int*)&g_P;
                double N = (double)*(volatile unsigned int*)&g_N;
                out[0] = (float)(acc / (P * N));
                g_P = 0u;
                g_N = 0u;
                g_done = 0u;
            }
        }
    }
}

// ---------------------------------------------------------------------------
extern "C" void kernel_launch(void* const* d_in, const int* in_sizes, int n_in,
                              void* d_out, int out_size) {
    const float* pred  = (const float*)d_in[0];
    const int*   label = (const int*)d_in[1];
    int total = in_sizes[0];   // n*K = 8192

    rul_tile_kernel<<<GRID, TPB>>>(pred, label, total, (float*)d_out);
}

// round 16
// speedup vs baseline: 1.0030x; 1.0030x over previous
#include <cuda_runtime.h>
#include <cuda_bf16.h>

// ONE kernel, ZERO inter-block sync. n=1024, K=8 -> 8192 entries.
//   total = sum_{a in pos, b in neg} log(1 + exp(v_b - v_a)) / (P*N)
//
// Tile decomposition: 16 ranges x 512 entries = 8192 EXACTLY. Block b=(i,j)
// compacts positives of range i and negatives of range j into SMEM in one
// pass, then computes its pos-tile x neg-tile pairs. 256 blocks cover every
// cross pair exactly once. 2 CTAs/SM, 1 wave.
//
// Pair math:
//   exp(q-p) = exp(q)*exp(-p);  sum log(1+t) = (log2 prod(t/64) + corr)*ln2
//   fma.rn.f32x2 / mul.rn.f32x2 packed: 1 instruction covers 2 pairs.
// MUFU-pressure fix (the measured bottleneck): per 128-pair unit, the four
// packed chain products are renormalized with ALU bit ops (biased exponents
// summed via shifts; mantissas forced to [1,2) via LOP3), the 8 mantissas
// multiplied together (3 mul2 + 1 fmul, product in [1,256)), and ONE
// __log2f taken -- 8x fewer MUFU.LG2 ops than one-log-per-chain.
// Per-unit constant: -8*127 (exponent bias) + 8*96 (16 t's * log2 64 per
// lane) = -248. Zero pads: t'=1/64 chain -> mant 1, biased exp 31;
// 0 + 31 - 127 + 96 = 0 -> exact cancellation.

#define RNG    16
#define RSZ    512            // 16*512 = 8192 exactly
#define GRID   (RNG * RNG)    // 256 <= 148*2 (one wave)
#define TPB    512
#define WARPS  (TPB / 32)
#define LCAP   544            // >= RSZ + 32 pad, multiple of 32
#define NSLOT  16

__device__ unsigned int g_P;        // global positive count   (reset per call)
__device__ unsigned int g_N;        // global negative count   (reset per call)
__device__ unsigned int g_done;     // finished blocks         (reset per call)
__device__ double g_accSlot[NSLOT];

typedef unsigned long long u64;

__device__ __forceinline__ u64 pk2(float lo, float hi) {
    u64 r; asm("mov.b64 %0, {%1, %2};" : "=l"(r) : "f"(lo), "f"(hi)); return r;
}
__device__ __forceinline__ void upk2(u64 v, float& lo, float& hi) {
    asm("mov.b64 {%0, %1}, %2;" : "=f"(lo), "=f"(hi) : "l"(v));
}
__device__ __forceinline__ u64 fma2(u64 a, u64 b, u64 c) {
    u64 d; asm("fma.rn.f32x2 %0, %1, %2, %3;" : "=l"(d) : "l"(a), "l"(b), "l"(c));
    return d;
}
__device__ __forceinline__ u64 mul2(u64 a, u64 b) {
    u64 d; asm("mul.rn.f32x2 %0, %1, %2;" : "=l"(d) : "l"(a), "l"(b));
    return d;
}
// Force both packed lanes' mantissas to [1,2) (values are positive, normal).
__device__ __forceinline__ u64 mant2(u64 v) {
    return (v & 0x007FFFFF007FFFFFull) | 0x3F8000003F800000ull;
}
// Sum of the two packed lanes' BIASED exponents (sign bits are 0).
__device__ __forceinline__ int esum2(u64 v) {
    unsigned lo = (unsigned)v, hi = (unsigned)(v >> 32);
    return (int)(lo >> 23) + (int)(hi >> 23);
}

__global__ void __launch_bounds__(TPB, 2)
rul_tile_kernel(const float* __restrict__ pred,
                const int* __restrict__ label,
                int total,
                float* __restrict__ out) {
    __shared__ __align__(16) float sPos[LCAP];   // exp(-v) list, zero padded
    __shared__ __align__(16) float sNeg[LCAP];   // exp(+v) list, zero padded
    __shared__ unsigned int sCntP, sCntN;
    __shared__ float sRed[WARPS];

    const unsigned lane = threadIdx.x & 31u;
    const unsigned warp = threadIdx.x >> 5;
    const unsigned ltmask = (1u << lane) - 1u;
    const int pi = blockIdx.x / RNG;     // positive range index
    const int nj = blockIdx.x % RNG;     // negative range index

    // ---- zero lists + counters ---------------------------------------------
    for (int k = (int)threadIdx.x; k < LCAP; k += TPB) {
        sPos[k] = 0.0f; sNeg[k] = 0.0f;
    }
    if (threadIdx.x == 0) { sCntP = 0u; sCntN = 0u; }
    __syncthreads();

    // ---- single-pass compaction: 1 pos + 1 neg element per thread ----------
    {
        int idx = (int)threadIdx.x;
        float vp = pred[pi * RSZ + idx];
        int   yp = label[pi * RSZ + idx];
        float vn = pred[nj * RSZ + idx];
        int   yn = label[nj * RSZ + idx];
        bool isPos = (yp == 1);
        bool isNeg = (yn == 0);

        unsigned mp = __ballot_sync(0xFFFFFFFFu, isPos);
        unsigned mn = __ballot_sync(0xFFFFFFFFu, isNeg);
        unsigned bp = 0, bn = 0;
        if (lane == 0) {
            if (mp) bp = atomicAdd(&sCntP, (unsigned)__popc(mp));
            if (mn) bn = atomicAdd(&sCntN, (unsigned)__popc(mn));
        }
        bp = __shfl_sync(0xFFFFFFFFu, bp, 0);
        bn = __shfl_sync(0xFFFFFFFFu, bn, 0);
        if (isPos) sPos[bp + __popc(mp & ltmask)] = __expf(-vp);
        if (isNeg) sNeg[bn + __popc(mn & ltmask)] = __expf(vn);
    }
    __syncthreads();

    const int cntP = (int)sCntP;
    const int cntN = (int)sCntN;

    // Contribute local counts to global P,N (each range counted once).
    if (threadIdx.x == 0) {
        if (nj == 0 && cntP) atomicAdd(&g_P, (unsigned)cntP);
        if (pi == 0 && cntN) atomicAdd(&g_N, (unsigned)cntN);
    }

    // ---- pair phase: 4 positives x 32 negatives per unit ---------------------
    int G4 = (cntP + 3) >> 2;                 // pos groups of 4
    if (G4 < 1) G4 = 1;
    int nCh = (cntN + 31) >> 5;               // neg chunks of 32 (8 ull2)
    const int units = G4 * nCh;               // ~512 typical (1/thread)

    const float4* __restrict__ posf4 =
        reinterpret_cast<const float4*>(sPos);
    const ulonglong2* __restrict__ negu =
        reinterpret_cast<const ulonglong2*>(sNeg);  // 1 ull2 = 4 negs
    const u64 S2 = pk2(0.015625f, 0.015625f); // 1/64

    float lgSum = 0.0f;
    int   nUnits = 0;
    for (int u = (int)threadIdx.x; u < units; u += TPB) {
        int chunk = u / G4;                   // consecutive threads share chunk
        int pg    = u - chunk * G4;

        float4 Fa = posf4[pg];                // 4 positives, coalesced
        u64 F0 = mul2(pk2(Fa.x, Fa.x), S2);   // lane-broadcast F/64
        u64 F1 = mul2(pk2(Fa.y, Fa.y), S2);
        u64 F2 = mul2(pk2(Fa.z, Fa.z), S2);
        u64 F3 = mul2(pk2(Fa.w, Fa.w), S2);

        const ulonglong2* qp = negu + chunk * 8;
        u64 m0, m1, m2, m3;
        {
            ulonglong2 qq = qp[0];
            m0 = mul2(fma2(qq.x, F0, S2), fma2(qq.y, F0, S2));
            m1 = mul2(fma2(qq.x, F1, S2), fma2(qq.y, F1, S2));
            m2 = mul2(fma2(qq.x, F2, S2), fma2(qq.y, F2, S2));
            m3 = mul2(fma2(qq.x, F3, S2), fma2(qq.y, F3, S2));
        }
#pragma unroll
        for (int k = 1; k < 8; ++k) {
            ulonglong2 qq = qp[k];
            m0 = mul2(m0, mul2(fma2(qq.x, F0, S2), fma2(qq.y, F0, S2)));
            m1 = mul2(m1, mul2(fma2(qq.x, F1, S2), fma2(qq.y, F1, S2)));
            m2 = mul2(m2, mul2(fma2(qq.x, F2, S2), fma2(qq.y, F2, S2)));
            m3 = mul2(m3, mul2(fma2(qq.x, F3, S2), fma2(qq.y, F3, S2)));
        }

        // ALU renorm: biased-exponent sum + mantissa product, ONE log2/unit.
        int e = esum2(m0) + esum2(m1) + esum2(m2) + esum2(m3);
        u64 a01 = mul2(mant2(m0), mant2(m1));   // lanes in [1,4)
        u64 a23 = mul2(mant2(m2), mant2(m3));
        u64 a   = mul2(a01, a23);               // lanes in [1,16)
        float x, y;
        upk2(a, x, y);
        lgSum += __log2f(x * y) + (float)e;     // x*y in [1,256)
        ++nUnits;
    }
    // Per-unit constant: -8*127 (bias) + 768 (16*log2(64) per lane * 8) = -248.
    float threadSum = (lgSum - 248.0f * (float)nUnits) * 0.6931471805599453f;

    // ---- block reduction ------------------------------------------------------
#pragma unroll
    for (int off = 16; off > 0; off >>= 1)
        threadSum += __shfl_down_sync(0xFFFFFFFFu, threadSum, off);
    if (lane == 0) sRed[warp] = threadSum;
    __syncthreads();
    if (warp == 0) {
        float s = (lane < WARPS) ? sRed[lane] : 0.0f;
#pragma unroll
        for (int off = 16; off > 0; off >>= 1)
            s += __shfl_down_sync(0xFFFFFFFFu, s, off);

        // ---- slotted accumulate + last-block finalize --------------------------
        if (lane == 0) {
            atomicAdd(&g_accSlot[blockIdx.x & (NSLOT - 1)], (double)s);
            __threadfence();
            unsigned int d = atomicAdd(&g_done, 1u);
            if (d == GRID - 1) {
                __threadfence();
                double acc = 0.0;
#pragma unroll
                for (int k = 0; k < NSLOT; ++k) {
                    acc += *(volatile double*)&g_accSlot[k];
                    g_accSlot[k] = 0.0;
                }
                double P = (double)*(volatile unsigned int*)&g_P;
                double N = (double)*(volatile unsigned int*)&g_N;
                out[0] = (float)(acc / (P * N));
                g_P = 0u;
                g_N = 0u;
                g_done = 0u;
            }
        }
    }
}

// ---------------------------------------------------------------------------
extern "C" void kernel_launch(void* const* d_in, const int* in_sizes, int n_in,
                              void* d_out, int out_size) {
    const float* pred  = (const float*)d_in[0];
    const int*   label = (const int*)d_in[1];
    int total = in_sizes[0];   // n*K = 8192

    rul_tile_kernel<<<GRID, TPB>>>(pred, label, total, (float*)d_out);
}